// round 16
// baseline (speedup 1.0000x reference)
#include <cuda_runtime.h>
#include <cuda_fp16.h>
#include <cstdint>

// Problem constants
#define NN   20000
#define BB   16
#define FF   64
#define CC   1024          // B*F columns of x
#define EE   640000
#define ODIM 64
#define KDIM 192

// GEMM tile: 128 rows x 64 cols, 256 threads (8 warps = 4m x 2n)
// A staged in 3-slab ring: slab = 64 k-cols (one diffusion matrix m)
#define BLK_M      128
#define SLAB_STRH  72       // halves per slab row (64 + 8 pad) -> 144 B
#define SLAB_BYTES (BLK_M * SLAB_STRH * 2)              // 18432
#define BS_STRH    72       // halves per B row (64 + 8 pad) -> 144 B
#define GEMM_SMEM  (3 * SLAB_BYTES + KDIM * BS_STRH * 2) // 82,944 B (2 CTAs/SM)

// Scratch (allocation-free rule: __device__ globals) — fp16 x arrays
__device__ __half g_x0[NN * CC];
__device__ __half g_x1[NN * CC];
__device__ __half g_x2[NN * CC];
__device__ int    g_rp[NN + 1];

__device__ __forceinline__ uint32_t smem_u32(const void* p) {
    uint32_t a;
    asm("{ .reg .u64 t; cvta.to.shared.u64 t, %1; cvt.u32.u64 %0, t; }" : "=r"(a) : "l"(p));
    return a;
}

__device__ __forceinline__ void mma_f16(float* d, const uint32_t* a, const uint32_t* b) {
    asm volatile(
        "mma.sync.aligned.m16n8k16.row.col.f32.f16.f16.f32 "
        "{%0,%1,%2,%3}, {%4,%5,%6,%7}, {%8,%9}, {%0,%1,%2,%3};"
        : "+f"(d[0]), "+f"(d[1]), "+f"(d[2]), "+f"(d[3])
        : "r"(a[0]), "r"(a[1]), "r"(a[2]), "r"(a[3]), "r"(b[0]), "r"(b[1]));
}
__device__ __forceinline__ void ldm_x4(uint32_t* r, uint32_t addr) {
    asm volatile("ldmatrix.sync.aligned.m8n8.x4.shared.b16 {%0,%1,%2,%3}, [%4];"
                 : "=r"(r[0]), "=r"(r[1]), "=r"(r[2]), "=r"(r[3]) : "r"(addr));
}
__device__ __forceinline__ void ldm_x4_t(uint32_t* r, uint32_t addr) {
    asm volatile("ldmatrix.sync.aligned.m8n8.x4.trans.shared.b16 {%0,%1,%2,%3}, [%4];"
                 : "=r"(r[0]), "=r"(r[1]), "=r"(r[2]), "=r"(r[3]) : "r"(addr));
}
__device__ __forceinline__ void cp_async16(uint32_t dst, const void* src, int src_bytes) {
    asm volatile("cp.async.ca.shared.global [%0], [%1], 16, %2;"
                 :: "r"(dst), "l"(src), "r"(src_bytes));
}
#define CP_COMMIT() asm volatile("cp.async.commit_group;" ::: "memory")
#define CP_WAIT1()  asm volatile("cp.async.wait_group 1;" ::: "memory")

// ---------------------------------------------------------------------------
// 1) Prelude: blocks [0,10000) pack inputs [B,N,F] fp32 -> x0 [N,B*F] fp16;
//    blocks [10000,12500) build row pointers from sorted rows.
// ---------------------------------------------------------------------------
#define PACK_BLOCKS   (NN * 128 / 256)        // 10000
#define RP_BLOCKS     ((EE + 255) / 256)      // 2500

__global__ void prelude_kernel(const float4* __restrict__ in4,
                               const int* __restrict__ rows) {
    if (blockIdx.x < PACK_BLOCKS) {
        int g  = blockIdx.x * 256 + threadIdx.x;   // 0 .. NN*128-1
        int f8 = g & 7;
        int b  = (g >> 3) & 15;
        int n  = g >> 7;
        float4 v0 = in4[(b * NN + n) * 16 + f8 * 2];
        float4 v1 = in4[(b * NN + n) * 16 + f8 * 2 + 1];
        __half2 h[4];
        h[0] = __float22half2_rn(make_float2(v0.x, v0.y));
        h[1] = __float22half2_rn(make_float2(v0.z, v0.w));
        h[2] = __float22half2_rn(make_float2(v1.x, v1.y));
        h[3] = __float22half2_rn(make_float2(v1.z, v1.w));
        ((uint4*)g_x0)[g] = *(uint4*)h;
    } else {
        int i = (blockIdx.x - PACK_BLOCKS) * 256 + threadIdx.x;
        if (i >= EE) return;
        int r    = rows[i];
        int prev = (i == 0) ? -1 : rows[i - 1];
        for (int rr = prev + 1; rr <= r; rr++) g_rp[rr] = i;
        if (i == EE - 1) {
            for (int rr = r + 1; rr <= NN; rr++) g_rp[rr] = EE;
        }
    }
}

// ---------------------------------------------------------------------------
// 2) SpMM fp16 (unchanged): block per row, 8-edge chunks, half2 chains,
//    streaming hints in phase 2.
// ---------------------------------------------------------------------------
template <int PHASE>
__global__ void __launch_bounds__(128) spmm_kernel(const int* __restrict__ cols,
                                                   const float* __restrict__ vals) {
    const uint4* __restrict__ x = (const uint4*)(PHASE == 1 ? g_x0 : g_x1);
    uint4* __restrict__ y       = (uint4*)(PHASE == 1 ? g_x1 : g_x2);

    int n = blockIdx.x;
    int t = threadIdx.x;
    int s = g_rp[n];
    int e = g_rp[n + 1];

    __shared__ int sc[128];
    __shared__ __align__(16) __half2 svh[128];

    float acc[8];
    #pragma unroll
    for (int q = 0; q < 8; q++) acc[q] = 0.f;

    for (int base = s; base < e; base += 128) {
        int cnt = min(128, e - base);
        __syncthreads();
        if (t < cnt) {
            sc[t]  = cols[base + t];
            svh[t] = __float2half2_rn(vals[base + t]);
        }
        __syncthreads();

        int j = 0;
        for (; j + 8 <= cnt; j += 8) {
            int cidx[8];
            *(int4*)&cidx[0] = *(const int4*)&sc[j];
            *(int4*)&cidx[4] = *(const int4*)&sc[j + 4];
            __half2 v[8];
            *(uint4*)&v[0] = *(const uint4*)&svh[j];
            *(uint4*)&v[4] = *(const uint4*)&svh[j + 4];
            uint4 xv[8];
            #pragma unroll
            for (int ee = 0; ee < 8; ee++) xv[ee] = x[cidx[ee] * 128 + t];
            #pragma unroll
            for (int q = 0; q < 4; q++) {
                __half2 h = __hmul2(((const __half2*)&xv[0])[q], v[0]);
                #pragma unroll
                for (int ee = 1; ee < 8; ee++)
                    h = __hfma2(((const __half2*)&xv[ee])[q], v[ee], h);
                float2 f = __half22float2(h);
                acc[q * 2]     += f.x;
                acc[q * 2 + 1] += f.y;
            }
        }
        for (; j + 4 <= cnt; j += 4) {
            int4 c4 = *(const int4*)&sc[j];
            __half2 v[4];
            *(uint4*)&v[0] = *(const uint4*)&svh[j];
            uint4 xv[4];
            xv[0] = x[c4.x * 128 + t];
            xv[1] = x[c4.y * 128 + t];
            xv[2] = x[c4.z * 128 + t];
            xv[3] = x[c4.w * 128 + t];
            #pragma unroll
            for (int q = 0; q < 4; q++) {
                __half2 h = __hmul2(((const __half2*)&xv[0])[q], v[0]);
                h = __hfma2(((const __half2*)&xv[1])[q], v[1], h);
                h = __hfma2(((const __half2*)&xv[2])[q], v[2], h);
                h = __hfma2(((const __half2*)&xv[3])[q], v[3], h);
                float2 f = __half22float2(h);
                acc[q * 2]     += f.x;
                acc[q * 2 + 1] += f.y;
            }
        }
        for (; j < cnt; j++) {
            __half2 va = svh[j];
            uint4 xv = x[sc[j] * 128 + t];
            const __half2* h = (const __half2*)&xv;
            #pragma unroll
            for (int q = 0; q < 4; q++) {
                float2 f = __half22float2(__hmul2(h[q], va));
                acc[q * 2]     += f.x;
                acc[q * 2 + 1] += f.y;
            }
        }
    }

    if (PHASE == 2) {
        uint4 x0v = __ldcs(((const uint4*)g_x0) + n * 128 + t);
        const __half2* h = (const __half2*)&x0v;
        #pragma unroll
        for (int q = 0; q < 4; q++) {
            float2 f = __half22float2(h[q]);
            acc[q * 2]     = 2.f * acc[q * 2]     - f.x;
            acc[q * 2 + 1] = 2.f * acc[q * 2 + 1] - f.y;
        }
    }

    __half2 hr[4];
    #pragma unroll
    for (int q = 0; q < 4; q++)
        hr[q] = __float22half2_rn(make_float2(acc[q * 2], acc[q * 2 + 1]));
    if (PHASE == 2) {
        __stcs(y + n * 128 + t, *(uint4*)hr);
    } else {
        y[n * 128 + t] = *(uint4*)hr;
    }
}

// ---------------------------------------------------------------------------
// 3) GEMM fp16 mma m16n8k16 + ldmatrix, slab-pipelined:
//    12 slabs (4 batches x 3 m-matrices), 3-buffer ring, cp.async depth 2.
// ---------------------------------------------------------------------------
__device__ __forceinline__ void prefetch_slab(uint32_t dst_base, int n0, int b,
                                              int m, int t) {
    const __half* __restrict__ src =
        (m == 0 ? (const __half*)g_x0 : (m == 1 ? (const __half*)g_x1
                                                : (const __half*)g_x2));
    for (int idx = t; idx < BLK_M * 8; idx += 256) {
        int q  = idx & 7;
        int nl = idx >> 3;
        int n  = n0 + nl;
        int nc = n < NN ? n : 0;
        uint32_t dst = dst_base + (uint32_t)(nl * SLAB_STRH + q * 8) * 2;
        cp_async16(dst, src + (size_t)nc * CC + b * 64 + q * 8, n < NN ? 16 : 0);
    }
    CP_COMMIT();
}

__global__ void __launch_bounds__(256, 2) gemm_mma_kernel(const float* __restrict__ weight,
                                                          const float* __restrict__ bias,
                                                          float* __restrict__ out) {
    extern __shared__ char sh[];
    __half* Bs = (__half*)(sh + 3 * SLAB_BYTES);      // [192][72] halves

    int t   = threadIdx.x;
    int wid = t >> 5;
    int lid = t & 31;
    int n0  = blockIdx.x * BLK_M;
    int b0  = blockIdx.y * 4;

    uint32_t As_base = smem_u32(sh);
    uint32_t Bs_base = smem_u32(Bs);

    // Prime the pipeline: slabs 0 and 1
    prefetch_slab(As_base,                n0, b0, 0, t);
    prefetch_slab(As_base + SLAB_BYTES,   n0, b0, 1, t);

    // Stage B once: weight[(f*3+m)][o] fp32 -> Bs[k=m*64+f][o] fp16
    for (int idx = t; idx < KDIM * 16; idx += 256) {
        int krow = idx >> 4;
        int o4   = idx & 15;
        int f    = krow & 63;
        int m    = krow >> 6;
        float4 w = ((const float4*)weight)[(f * 3 + m) * 16 + o4];
        __half2 h2[2];
        h2[0] = __float22half2_rn(make_float2(w.x, w.y));
        h2[1] = __float22half2_rn(make_float2(w.z, w.w));
        *(uint2*)(Bs + krow * BS_STRH + o4 * 4) = *(uint2*)h2;
    }

    int wm = wid & 3;                    // 4 m-warps
    int wn = wid >> 2;                   // 2 n-warps
    int grp = lid >> 2;                  // 0..7
    int tig = lid & 3;                   // 0..3
    int tl = lid >> 3;                   // ldmatrix tile 0..3
    int lr = (lid & 7) + (tl & 1) * 8;   // row within 16
    int lk = (tl >> 1) * 8;              // half-col offset within 16

    float d[2][4][4];

    #pragma unroll 1
    for (int s = 0; s < 12; s++) {
        int m = s - (s / 3) * 3;         // s % 3
        int b = b0 + s / 3;

        if (m == 0) {
            #pragma unroll
            for (int i = 0; i < 2; i++)
                #pragma unroll
                for (int j = 0; j < 4; j++)
                    #pragma unroll
                    for (int q = 0; q < 4; q++) d[i][j][q] = 0.f;
        }

        CP_WAIT1();                       // slab s landed (s+1 may be in flight)
        __syncthreads();

        uint32_t As_cur = As_base + (uint32_t)(m == 0 ? 0 : (m == 1 ? 1 : 2))
                                    * 0;  // placeholder, replaced below
        As_cur = As_base + (uint32_t)((s - (s / 3) * 3 + (s / 3) * 3) % 3) * SLAB_BYTES;
        // simpler: ring index = s % 3
        As_cur = As_base + (uint32_t)(s % 3) * SLAB_BYTES;

        #pragma unroll
        for (int ks = 0; ks < 4; ks++) {
            int k0l = ks * 16;                    // k within slab
            int k0g = m * 64 + k0l;               // global k for B
            uint32_t a[2][4], bq[2][4];
            #pragma unroll
            for (int i = 0; i < 2; i++) {
                uint32_t addr = As_cur + (uint32_t)((wm * 32 + i * 16 + lr) * (SLAB_STRH * 2)
                                                     + (k0l + lk) * 2);
                ldm_x4(a[i], addr);
            }
            #pragma unroll
            for (int jj = 0; jj < 2; jj++) {
                uint32_t addr = Bs_base + (uint32_t)((k0g + lr) * (BS_STRH * 2)
                                                     + (wn * 32 + jj * 16 + lk) * 2);
                ldm_x4_t(bq[jj], addr);
            }
            #pragma unroll
            for (int i = 0; i < 2; i++) {
                #pragma unroll
                for (int j = 0; j < 4; j++) {
                    uint32_t bb[2] = { bq[j >> 1][(j & 1) * 2], bq[j >> 1][(j & 1) * 2 + 1] };
                    mma_f16(d[i][j], a[i], bb);
                }
            }
        }

        __syncthreads();                  // all warps done with buffer s%3 epoch
        if (s + 2 < 12) {
            prefetch_slab(As_base + (uint32_t)((s + 2) % 3) * SLAB_BYTES,
                          n0, b0 + (s + 2) / 3, (s + 2) % 3, t);
        } else {
            CP_COMMIT();                  // keep group count in lockstep
        }

        if (m == 2) {
            // Epilogue for batch b (overlaps the in-flight prefetches)
            #pragma unroll
            for (int i = 0; i < 2; i++) {
                #pragma unroll
                for (int j = 0; j < 4; j++) {
                    int cc = wn * 32 + j * 8 + 2 * tig;
                    float2 bb = *(const float2*)(bias + cc);
                    int rn = n0 + wm * 32 + i * 16 + grp;
                    if (rn < NN) {
                        float2 v = make_float2(d[i][j][0] + bb.x, d[i][j][1] + bb.y);
                        __stcs((float2*)(out + ((long long)b * NN + rn) * ODIM + cc), v);
                    }
                    int rn2 = rn + 8;
                    if (rn2 < NN) {
                        float2 v = make_float2(d[i][j][2] + bb.x, d[i][j][3] + bb.y);
                        __stcs((float2*)(out + ((long long)b * NN + rn2) * ODIM + cc), v);
                    }
                }
            }
        }
    }
}

// ---------------------------------------------------------------------------
// Launch
// ---------------------------------------------------------------------------
extern "C" void kernel_launch(void* const* d_in, const int* in_sizes, int n_in,
                              void* d_out, int out_size) {
    const float4* inputs = (const float4*)d_in[0];
    const int*    rows   = (const int*)d_in[1];
    const int*    cols   = (const int*)d_in[2];
    const float*  vals   = (const float*)d_in[3];
    const float*  weight = (const float*)d_in[4];
    const float*  bias   = (const float*)d_in[5];
    float*        out    = (float*)d_out;

    cudaFuncSetAttribute(gemm_mma_kernel, cudaFuncAttributeMaxDynamicSharedMemorySize,
                         GEMM_SMEM);

    prelude_kernel<<<PACK_BLOCKS + RP_BLOCKS, 256>>>(inputs, rows);
    spmm_kernel<1><<<NN, 128>>>(cols, vals);
    spmm_kernel<2><<<NN, 128>>>(cols, vals);
    gemm_mma_kernel<<<dim3((NN + BLK_M - 1) / BLK_M, 4), 256, GEMM_SMEM>>>(weight, bias, out);
}